// round 3
// baseline (speedup 1.0000x reference)
#include <cuda_runtime.h>

#define HW 4096
#define NR 2048
#define NL 16

// ---------------- device scratch ----------------
__device__ float d_S[NR];
__device__ int   d_gcount[NL], d_gstart[NL];
__device__ int   d_nvalid;
__device__ int   d_prow[NR], d_pgrp[NR];
__device__ float d_pwq[NR], d_pbq[NR], d_pwk[NR], d_pbk[NR], d_pwv[NR], d_pbv[NR];
__device__ int   d_pmq[NR], d_pnk[NR], d_pnv[NR];
__device__ float d_pSq[NR], d_pSk[NR];
__device__ float d_cst[NR];
__device__ float d_scores[(long long)NR * NR];

#define MAXWS 128
#define MAXWO 64
__device__ int d_wsG[MAXWS], d_wsA[MAXWS], d_wsB[MAXWS], d_nWorkS;
__device__ int d_woG[MAXWO], d_woA[MAXWO], d_nWorkO;

// ---------------- f32x2 helpers ----------------
__device__ __forceinline__ unsigned long long dup2(float v) {
    unsigned long long r;
    asm("mov.b64 %0, {%1, %1};" : "=l"(r) : "f"(v));
    return r;
}
__device__ __forceinline__ void fma2(unsigned long long &d, unsigned long long a,
                                     unsigned long long b) {
    asm("fma.rn.f32x2 %0, %1, %2, %0;" : "+l"(d) : "l"(a), "l"(b));
}
__device__ __forceinline__ float2 unpk(unsigned long long v) {
    float2 r;
    asm("mov.b64 {%0, %1}, %2;" : "=f"(r.x), "=f"(r.y) : "l"(v));
    return r;
}
__device__ __forceinline__ unsigned long long pk2(float a, float b) {
    unsigned long long r;
    asm("mov.b64 %0, {%1, %2};" : "=l"(r) : "f"(a), "f"(b));
    return r;
}

// ---------------- setup ----------------
__global__ void setupKernel(const int* __restrict__ labels) {
    __shared__ int cnt[NL];
    int t = threadIdx.x;
    if (t < NL) cnt[t] = 0;
    __syncthreads();
    for (int i = t; i < NR; i += 256) {
        int l = labels[i];
        if (l >= 0) atomicAdd(&cnt[l], 1);
    }
    __syncthreads();
    if (t == 0) {
        int s = 0;
        for (int l = 0; l < NL; l++) { d_gcount[l] = cnt[l]; d_gstart[l] = s; s += cnt[l]; }
        d_nvalid = s;
        int n = 0;
        for (int l = 0; l < NL; l++) {
            int T = (cnt[l] + 127) / 128;
            for (int a = 0; a < T; a++)
                for (int b = 0; b < T; b++)
                    if (n < MAXWS) { d_wsG[n] = l; d_wsA[n] = a; d_wsB[n] = b; n++; }
        }
        d_nWorkS = n;
        n = 0;
        for (int l = 0; l < NL; l++) {
            int T = (cnt[l] + 127) / 128;
            for (int a = 0; a < T; a++)
                if (n < MAXWO) { d_woG[n] = l; d_woA[n] = a; n++; }
        }
        d_nWorkO = n;
    }
}

__global__ void rowsumKernel(const float* __restrict__ x) {
    int m = blockIdx.x;
    const float4* p = (const float4*)(x + (long long)m * HW);
    float s = 0.f;
    for (int i = threadIdx.x; i < HW / 4; i += 128) {
        float4 v = p[i];
        s += (v.x + v.y) + (v.z + v.w);
    }
    __shared__ float red[128];
    red[threadIdx.x] = s;
    __syncthreads();
    for (int o = 64; o > 0; o >>= 1) {
        if (threadIdx.x < o) red[threadIdx.x] += red[threadIdx.x + o];
        __syncthreads();
    }
    if (threadIdx.x == 0) d_S[m] = red[0];
}

__global__ void scatterKernel(const int* __restrict__ labels,
                              const float* __restrict__ w,
                              const float* __restrict__ bb) {
    __shared__ int sl[NR];
    for (int j = threadIdx.x; j < NR; j += 128) sl[j] = labels[j];
    __syncthreads();
    int i = blockIdx.x * 128 + threadIdx.x;
    int l = sl[i];
    if (l < 0) return;
    int rank = 0;
    for (int j = 0; j < i; j++) rank += (sl[j] == l);
    int pos = d_gstart[l] + rank;
    d_prow[pos] = i;
    d_pgrp[pos] = l;
    int jq = i % 768;            int mq = (i / 768) * 256 + jq / 3;
    int rk = i + 2048; int jk = rk % 768; int nk = (rk / 768) * 256 + jk / 3;
    int rv = i + 4096; int jv = rv % 768; int nv = (rv / 768) * 256 + jv / 3;
    d_pwq[pos] = w[jq]; d_pbq[pos] = bb[jq];
    d_pwk[pos] = w[jk]; d_pbk[pos] = bb[jk];
    d_pwv[pos] = w[jv]; d_pbv[pos] = bb[jv];
    d_pmq[pos] = mq; d_pnk[pos] = nk; d_pnv[pos] = nv;
    d_pSq[pos] = d_S[mq]; d_pSk[pos] = d_S[nk];
}

// affine part of scores (warp per row)
__global__ void scoreInitKernel() {
    int p = blockIdx.x * 8 + (threadIdx.x >> 5);
    int lane = threadIdx.x & 31;
    if (p >= d_nvalid) return;
    int g = d_pgrp[p], gs = d_gstart[g], gc = d_gcount[g];
    float wq = d_pwq[p], bq = d_pbq[p], Sq = d_pSq[p];
    long long ro = (long long)p * NR;
    for (int bl = lane; bl < gc; bl += 32) {
        int q = gs + bl;
        d_scores[ro + bl] = wq * d_pbk[q] * Sq + bq * d_pwk[q] * d_pSk[q]
                          + bq * d_pbk[q] * (float)HW;
    }
}

// ---------------- scores GEMM: 128x128 tile, splitK=8, conflict-free ----
// microtile: rows {ty*4, 64+ty*4}, cols {tx*4, 64+tx*4}; all frags LDS.128
__global__ __launch_bounds__(256) void scoresGemmKernel(const float* __restrict__ x) {
    int wi = blockIdx.x >> 3;
    int ks = blockIdx.x & 7;
    if (wi >= d_nWorkS) return;
    int g = d_wsG[wi];
    int gs = d_gstart[g], gc = d_gcount[g];
    int a0 = d_wsA[wi] * 128, b0 = d_wsB[wi] * 128;
    int k0b = ks * (HW / 8);

    __shared__ float As[2][8][132], Bs[2][8][132];
    int tid = threadIdx.x;
    int ty = tid >> 4, tx = tid & 15;
    int lr = tid >> 1, lk = (tid & 1) * 4;

    const float* ap  = (a0 + lr < gc) ? x + (long long)d_pmq[gs + a0 + lr] * HW + k0b + lk : 0;
    const float* bpp = (b0 + lr < gc) ? x + (long long)d_pnk[gs + b0 + lr] * HW + k0b + lk : 0;

    unsigned long long acc[8][4];
#pragma unroll
    for (int r = 0; r < 8; r++)
#pragma unroll
        for (int c = 0; c < 4; c++) acc[r][c] = 0ull;

    float4 z4 = make_float4(0, 0, 0, 0);
    float4 va = ap  ? *(const float4*)ap  : z4;
    float4 vb = bpp ? *(const float4*)bpp : z4;
    As[0][lk + 0][lr] = va.x; As[0][lk + 1][lr] = va.y;
    As[0][lk + 2][lr] = va.z; As[0][lk + 3][lr] = va.w;
    Bs[0][lk + 0][lr] = vb.x; Bs[0][lk + 1][lr] = vb.y;
    Bs[0][lk + 2][lr] = vb.z; Bs[0][lk + 3][lr] = vb.w;
    __syncthreads();

    for (int kc = 0; kc < 64; kc++) {
        int cur = kc & 1;
        if (kc < 63) {
            va = ap  ? *(const float4*)(ap  + (kc + 1) * 8) : z4;
            vb = bpp ? *(const float4*)(bpp + (kc + 1) * 8) : z4;
        }
#pragma unroll
        for (int kk = 0; kk < 8; kk++) {
            float4 aA = *(const float4*)&As[cur][kk][ty * 4];
            float4 aB = *(const float4*)&As[cur][kk][64 + ty * 4];
            float4 bA = *(const float4*)&Bs[cur][kk][tx * 4];
            float4 bB = *(const float4*)&Bs[cur][kk][64 + tx * 4];
            unsigned long long bd[4] = { pk2(bA.x, bA.y), pk2(bA.z, bA.w),
                                         pk2(bB.x, bB.y), pk2(bB.z, bB.w) };
            unsigned long long ad[8] = { dup2(aA.x), dup2(aA.y), dup2(aA.z), dup2(aA.w),
                                         dup2(aB.x), dup2(aB.y), dup2(aB.z), dup2(aB.w) };
#pragma unroll
            for (int r = 0; r < 8; r++)
#pragma unroll
                for (int c = 0; c < 4; c++) fma2(acc[r][c], ad[r], bd[c]);
        }
        if (kc < 63) {
            int nx = cur ^ 1;
            As[nx][lk + 0][lr] = va.x; As[nx][lk + 1][lr] = va.y;
            As[nx][lk + 2][lr] = va.z; As[nx][lk + 3][lr] = va.w;
            Bs[nx][lk + 0][lr] = vb.x; Bs[nx][lk + 1][lr] = vb.y;
            Bs[nx][lk + 2][lr] = vb.z; Bs[nx][lk + 3][lr] = vb.w;
            __syncthreads();
        }
    }

#pragma unroll
    for (int r = 0; r < 8; r++) {
        int al = a0 + ((r < 4) ? ty * 4 + r : 64 + ty * 4 + (r - 4));
        if (al >= gc) continue;
        int p = gs + al;
        float wq = d_pwq[p];
        long long ro = (long long)p * NR;
#pragma unroll
        for (int c = 0; c < 4; c++) {
            float2 v = unpk(acc[r][c]);
            int col = b0 + ((c < 2) ? tx * 4 + c * 2 : 64 + tx * 4 + (c - 2) * 2);
            if (col < gc)     atomicAdd(&d_scores[ro + col],     wq * d_pwk[gs + col] * v.x);
            if (col + 1 < gc) atomicAdd(&d_scores[ro + col + 1], wq * d_pwk[gs + col + 1] * v.y);
        }
    }
}

// ---------------- softmax + fold wv/bv, warp per row --------------------
__global__ void softmaxKernel() {
    int p = blockIdx.x * 8 + (threadIdx.x >> 5);
    int lane = threadIdx.x & 31;
    if (p >= d_nvalid) return;
    int g = d_pgrp[p], gs = d_gstart[g], gc = d_gcount[g];
    long long ro = (long long)p * NR;

    float m = -3.4e38f;
    for (int bl = lane; bl < gc; bl += 32) m = fmaxf(m, d_scores[ro + bl]);
#pragma unroll
    for (int o = 16; o > 0; o >>= 1) m = fmaxf(m, __shfl_xor_sync(0xffffffffu, m, o));

    float sum = 0.f, cs = 0.f;
    for (int bl = lane; bl < gc; bl += 32) {
        float e = expf(d_scores[ro + bl] - m);
        d_scores[ro + bl] = e;
        sum += e;
        cs += e * d_pbv[gs + bl];
    }
#pragma unroll
    for (int o = 16; o > 0; o >>= 1) {
        sum += __shfl_xor_sync(0xffffffffu, sum, o);
        cs  += __shfl_xor_sync(0xffffffffu, cs, o);
    }
    float inv = 1.0f / sum;
    for (int bl = lane; bl < gc; bl += 32)
        d_scores[ro + bl] *= inv * d_pwv[gs + bl];
    if (lane == 0) d_cst[p] = cs * inv;
}

// ---------------- out GEMM: conflict-free microtile ---------------------
__global__ __launch_bounds__(256) void outGemmKernel(const float* __restrict__ x,
                                                     float* __restrict__ out) {
    int wi = blockIdx.x >> 5;
    if (wi >= d_nWorkO) return;
    int t0 = (blockIdx.x & 31) * 128;
    int g = d_woG[wi];
    int gs = d_gstart[g], gc = d_gcount[g];
    int a0 = d_woA[wi] * 128;

    __shared__ float Cs[2][8][132], Xs[2][8][132];
    int tid = threadIdx.x, ty = tid >> 4, tx = tid & 15;
    int lr = tid >> 1, lk = (tid & 1) * 4;
    int xk = tid >> 5, xc = (tid & 31) * 4;

    unsigned long long acc[8][4];
#pragma unroll
    for (int r = 0; r < 8; r++)
#pragma unroll
        for (int c = 0; c < 4; c++) acc[r][c] = 0ull;

    long long crow = (a0 + lr < gc) ? (long long)(gs + a0 + lr) * NR : -1;
    int nIter = (gc + 7) >> 3;
    float4 z4 = make_float4(0, 0, 0, 0);

    float4 vc = z4, vx;
    {
        if (crow >= 0) {
            vc = *(const float4*)&d_scores[crow + lk];
            if (lk + 0 >= gc) vc.x = 0.f;
            if (lk + 1 >= gc) vc.y = 0.f;
            if (lk + 2 >= gc) vc.z = 0.f;
            if (lk + 3 >= gc) vc.w = 0.f;
        }
        int vrow = (xk < gc) ? d_pnv[gs + xk] : 0;
        vx = *(const float4*)&x[(long long)vrow * HW + t0 + xc];
    }
    Cs[0][lk + 0][lr] = vc.x; Cs[0][lk + 1][lr] = vc.y;
    Cs[0][lk + 2][lr] = vc.z; Cs[0][lk + 3][lr] = vc.w;
    *(float4*)&Xs[0][xk][xc] = vx;
    __syncthreads();

    for (int it = 0; it < nIter; it++) {
        int cur = it & 1;
        if (it + 1 < nIter) {
            int b0 = (it + 1) * 8;
            vc = z4;
            if (crow >= 0) {
                vc = *(const float4*)&d_scores[crow + b0 + lk];
                if (b0 + lk + 0 >= gc) vc.x = 0.f;
                if (b0 + lk + 1 >= gc) vc.y = 0.f;
                if (b0 + lk + 2 >= gc) vc.z = 0.f;
                if (b0 + lk + 3 >= gc) vc.w = 0.f;
            }
            int bm = b0 + xk;
            int vrow = (bm < gc) ? d_pnv[gs + bm] : 0;
            vx = *(const float4*)&x[(long long)vrow * HW + t0 + xc];
        }
#pragma unroll
        for (int kk = 0; kk < 8; kk++) {
            float4 aA = *(const float4*)&Cs[cur][kk][ty * 4];
            float4 aB = *(const float4*)&Cs[cur][kk][64 + ty * 4];
            float4 bA = *(const float4*)&Xs[cur][kk][tx * 4];
            float4 bB = *(const float4*)&Xs[cur][kk][64 + tx * 4];
            unsigned long long bd[4] = { pk2(bA.x, bA.y), pk2(bA.z, bA.w),
                                         pk2(bB.x, bB.y), pk2(bB.z, bB.w) };
            unsigned long long ad[8] = { dup2(aA.x), dup2(aA.y), dup2(aA.z), dup2(aA.w),
                                         dup2(aB.x), dup2(aB.y), dup2(aB.z), dup2(aB.w) };
#pragma unroll
            for (int r = 0; r < 8; r++)
#pragma unroll
                for (int c = 0; c < 4; c++) fma2(acc[r][c], ad[r], bd[c]);
        }
        if (it + 1 < nIter) {
            int nx = cur ^ 1;
            Cs[nx][lk + 0][lr] = vc.x; Cs[nx][lk + 1][lr] = vc.y;
            Cs[nx][lk + 2][lr] = vc.z; Cs[nx][lk + 3][lr] = vc.w;
            *(float4*)&Xs[nx][xk][xc] = vx;
            __syncthreads();
        }
    }

#pragma unroll
    for (int r = 0; r < 8; r++) {
        int al = a0 + ((r < 4) ? ty * 4 + r : 64 + ty * 4 + (r - 4));
        if (al >= gc) continue;
        int p = gs + al;
        int row = d_prow[p];
        float cst = d_cst[p];
        float* op = out + (long long)row * HW + t0;
#pragma unroll
        for (int c = 0; c < 4; c++) {
            float2 v = unpk(acc[r][c]);
            int col = (c < 2) ? tx * 4 + c * 2 : 64 + tx * 4 + (c - 2) * 2;
            op[col]     = v.x + cst;
            op[col + 1] = v.y + cst;
        }
    }
}

// ---------------- launch ----------------
extern "C" void kernel_launch(void* const* d_in, const int* in_sizes, int n_in,
                              void* d_out, int out_size) {
    const float* x      = (const float*)d_in[0];
    const int*   labels = (const int*)d_in[1];
    const float* w      = (const float*)d_in[2];
    const float* bb     = (const float*)d_in[3];
    float* out = (float*)d_out;

    cudaMemsetAsync(d_out, 0, (size_t)out_size * sizeof(float), 0);
    rowsumKernel<<<NR, 128>>>(x);
    setupKernel<<<1, 256>>>(labels);
    scatterKernel<<<16, 128>>>(labels, w, bb);
    scoreInitKernel<<<256, 256>>>();
    scoresGemmKernel<<<MAXWS * 8, 256>>>(x);
    softmaxKernel<<<256, 256>>>();
    outGemmKernel<<<MAXWO * 32, 256>>>(x, out);
    (void)in_sizes; (void)n_in;
}

// round 4
// speedup vs baseline: 1.5953x; 1.5953x over previous
#include <cuda_runtime.h>

#define HW 4096
#define NR 2048
#define NL 16
#define NRC 256          // group-local column capacity

// ---------------- device scratch ----------------
__device__ float d_S[NR];
__device__ int   d_gcount[NL], d_gstart[NL];
__device__ int   d_nvalid;
__device__ int   d_prow[NR], d_pgrp[NR];
__device__ float d_pwq[NR], d_pbq[NR], d_pwk[NR], d_pbk[NR], d_pwv[NR], d_pbv[NR];
__device__ int   d_pmq[NR], d_pnk[NR], d_pnv[NR];
__device__ float d_pSq[NR], d_pSk[NR];
__device__ float d_cst[NR];
__device__ float d_scores[(long long)NR * NRC];              // 2 MB coeff matrix
__device__ float d_part[8ll * NR * NRC];                     // 16 MB splitK partials

#define MAXWS 128
#define MAXWO 64
__device__ int d_wsG[MAXWS], d_wsA[MAXWS], d_wsB[MAXWS], d_nWorkS;
__device__ int d_woG[MAXWO], d_woA[MAXWO], d_nWorkO;

// ---------------- f32x2 helpers ----------------
__device__ __forceinline__ unsigned long long dup2(float v) {
    unsigned long long r;
    asm("mov.b64 %0, {%1, %1};" : "=l"(r) : "f"(v));
    return r;
}
__device__ __forceinline__ void fma2(unsigned long long &d, unsigned long long a,
                                     unsigned long long b) {
    asm("fma.rn.f32x2 %0, %1, %2, %0;" : "+l"(d) : "l"(a), "l"(b));
}
__device__ __forceinline__ float2 unpk(unsigned long long v) {
    float2 r;
    asm("mov.b64 {%0, %1}, %2;" : "=f"(r.x), "=f"(r.y) : "l"(v));
    return r;
}

// ---------------- rowsum ----------------
__global__ void rowsumKernel(const float* __restrict__ x) {
    int m = blockIdx.x;
    const float4* p = (const float4*)(x + (long long)m * HW);
    float s = 0.f;
    for (int i = threadIdx.x; i < HW / 4; i += 128) {
        float4 v = p[i];
        s += (v.x + v.y) + (v.z + v.w);
    }
    __shared__ float red[128];
    red[threadIdx.x] = s;
    __syncthreads();
    for (int o = 64; o > 0; o >>= 1) {
        if (threadIdx.x < o) red[threadIdx.x] += red[threadIdx.x + o];
        __syncthreads();
    }
    if (threadIdx.x == 0) d_S[m] = red[0];
}

// ---------------- scatter: self-contained setup + grouping ----------------
__global__ void scatterKernel(const int* __restrict__ labels,
                              const float* __restrict__ w,
                              const float* __restrict__ bb) {
    __shared__ int sl[NR];
    __shared__ int cnt[NL], sst[NL];
    int t = threadIdx.x;
    if (t < NL) cnt[t] = 0;
    for (int j = t; j < NR; j += 128) sl[j] = labels[j];
    __syncthreads();
    for (int j = t; j < NR; j += 128) {
        int l = sl[j];
        if (l >= 0) atomicAdd(&cnt[l], 1);
    }
    __syncthreads();
    if (t == 0) {
        int s = 0;
        for (int l = 0; l < NL; l++) { sst[l] = s; s += cnt[l]; }
        if (blockIdx.x == 0) {
            d_nvalid = s;
            for (int l = 0; l < NL; l++) { d_gcount[l] = cnt[l]; d_gstart[l] = sst[l]; }
            int n = 0;
            for (int l = 0; l < NL; l++) {
                int T = (cnt[l] + 127) / 128;
                for (int a = 0; a < T; a++)
                    for (int b = 0; b < T; b++)
                        if (n < MAXWS) { d_wsG[n] = l; d_wsA[n] = a; d_wsB[n] = b; n++; }
            }
            d_nWorkS = n;
            n = 0;
            for (int l = 0; l < NL; l++) {
                int T = (cnt[l] + 127) / 128;
                for (int a = 0; a < T; a++)
                    if (n < MAXWO) { d_woG[n] = l; d_woA[n] = a; n++; }
            }
            d_nWorkO = n;
        }
    }
    __syncthreads();
    int i = blockIdx.x * 128 + t;
    int l = sl[i];
    if (l < 0) return;
    int rank = 0;
    for (int j = 0; j < i; j++) rank += (sl[j] == l);
    int pos = sst[l] + rank;
    d_prow[pos] = i;
    d_pgrp[pos] = l;
    int jq = i % 768;            int mq = (i / 768) * 256 + jq / 3;
    int rk = i + 2048; int jk = rk % 768; int nk = (rk / 768) * 256 + jk / 3;
    int rv = i + 4096; int jv = rv % 768; int nv = (rv / 768) * 256 + jv / 3;
    d_pwq[pos] = w[jq]; d_pbq[pos] = bb[jq];
    d_pwk[pos] = w[jk]; d_pbk[pos] = bb[jk];
    d_pwv[pos] = w[jv]; d_pbv[pos] = bb[jv];
    d_pmq[pos] = mq; d_pnk[pos] = nk; d_pnv[pos] = nv;
    d_pSq[pos] = d_S[mq]; d_pSk[pos] = d_S[nk];
}

// ---------------- zero only invalid output rows ----------------
__global__ void zeroInvalidKernel(const int* __restrict__ labels,
                                  float* __restrict__ out) {
    int i = blockIdx.x;
    if (labels[i] >= 0) return;
    float4* p = (float4*)(out + (long long)i * HW);
    float4 z = make_float4(0, 0, 0, 0);
    for (int j = threadIdx.x; j < HW / 4; j += 128) p[j] = z;
}

// ---------------- scores GEMM (R1 core): raw Gram partials, no atomics ---
__global__ __launch_bounds__(256) void scoresGemmKernel(const float* __restrict__ x) {
    int wi = blockIdx.x >> 3;
    int ks = blockIdx.x & 7;
    if (wi >= d_nWorkS) return;
    int g = d_wsG[wi];
    int gs = d_gstart[g], gc = d_gcount[g];
    int a0 = d_wsA[wi] * 128, b0 = d_wsB[wi] * 128;
    int k0b = ks * (HW / 8);

    __shared__ float As[8][132], Bs[8][132];
    int tid = threadIdx.x;
    int ty = tid >> 4, tx = tid & 15;

    unsigned long long acc[8][4];
#pragma unroll
    for (int r = 0; r < 8; r++)
#pragma unroll
        for (int c = 0; c < 4; c++) acc[r][c] = 0ull;

    int lr = tid >> 1, lk = (tid & 1) * 4;
    const float* ap  = (a0 + lr < gc) ? x + (long long)d_pmq[gs + a0 + lr] * HW : 0;
    const float* bpp = (b0 + lr < gc) ? x + (long long)d_pnk[gs + b0 + lr] * HW : 0;

    for (int kc = 0; kc < 64; kc++) {
        int k0 = k0b + kc * 8 + lk;
        float4 va = ap  ? *(const float4*)(ap  + k0) : make_float4(0, 0, 0, 0);
        float4 vb = bpp ? *(const float4*)(bpp + k0) : make_float4(0, 0, 0, 0);
        __syncthreads();
        As[lk + 0][lr] = va.x; As[lk + 1][lr] = va.y;
        As[lk + 2][lr] = va.z; As[lk + 3][lr] = va.w;
        Bs[lk + 0][lr] = vb.x; Bs[lk + 1][lr] = vb.y;
        Bs[lk + 2][lr] = vb.z; Bs[lk + 3][lr] = vb.w;
        __syncthreads();
#pragma unroll
        for (int kk = 0; kk < 8; kk++) {
            unsigned long long ad[8], bd[4];
#pragma unroll
            for (int r = 0; r < 8; r++) ad[r] = dup2(As[kk][ty * 8 + r]);
#pragma unroll
            for (int c = 0; c < 4; c++)
                bd[c] = *(const unsigned long long*)&Bs[kk][tx * 8 + c * 2];
#pragma unroll
            for (int r = 0; r < 8; r++)
#pragma unroll
                for (int c = 0; c < 4; c++) fma2(acc[r][c], ad[r], bd[c]);
        }
    }

    // store raw Gram partials (wq/wk scaling folded into softmax)
    long long kbase = (long long)ks * NR * NRC;
#pragma unroll
    for (int r = 0; r < 8; r++) {
        int al = a0 + ty * 8 + r;
        if (al >= gc) continue;
        long long ro = kbase + (long long)(gs + al) * NRC;
#pragma unroll
        for (int c = 0; c < 4; c++) {
            int col = b0 + tx * 8 + c * 2;
            if (col + 1 < gc) {
                *(unsigned long long*)&d_part[ro + col] = acc[r][c];
            } else if (col < gc) {
                d_part[ro + col] = unpk(acc[r][c]).x;
            }
        }
    }
}

// ---------------- softmax: 8-way partial sum + affine + softmax + wv fold
__global__ void softmaxKernel() {
    int p = blockIdx.x * 8 + (threadIdx.x >> 5);
    int lane = threadIdx.x & 31;
    if (p >= d_nvalid) return;
    int g = d_pgrp[p], gs = d_gstart[g], gc = d_gcount[g];
    long long ro = (long long)p * NRC;

    float wq = d_pwq[p], bq = d_pbq[p];
    float A2 = wq * d_pSq[p] + bq * (float)HW;   // coeff of bk_q

    // pass 1: reduce partials + affine -> d_scores, track max
    float m = -3.4e38f;
    for (int bl = lane; bl < gc; bl += 32) {
        float gsum = 0.f;
#pragma unroll
        for (int s = 0; s < 8; s++) gsum += d_part[(long long)s * NR * NRC + ro + bl];
        int q = gs + bl;
        float val = d_pwk[q] * (wq * gsum + bq * d_pSk[q]) + A2 * d_pbk[q];
        d_scores[ro + bl] = val;
        m = fmaxf(m, val);
    }
#pragma unroll
    for (int o = 16; o > 0; o >>= 1) m = fmaxf(m, __shfl_xor_sync(0xffffffffu, m, o));

    float sum = 0.f, cs = 0.f;
    for (int bl = lane; bl < gc; bl += 32) {
        float e = expf(d_scores[ro + bl] - m);
        d_scores[ro + bl] = e;
        sum += e;
        cs += e * d_pbv[gs + bl];
    }
#pragma unroll
    for (int o = 16; o > 0; o >>= 1) {
        sum += __shfl_xor_sync(0xffffffffu, sum, o);
        cs  += __shfl_xor_sync(0xffffffffu, cs, o);
    }
    float inv = 1.0f / sum;
    for (int bl = lane; bl < gc; bl += 32)
        d_scores[ro + bl] *= inv * d_pwv[gs + bl];
    if (lane == 0) d_cst[p] = cs * inv;
}

// ---------------- out GEMM (R1 core): coeff (g x g) @ Xv (g x 4096) ------
__global__ __launch_bounds__(256) void outGemmKernel(const float* __restrict__ x,
                                                     float* __restrict__ out) {
    int wi = blockIdx.x >> 5;
    if (wi >= d_nWorkO) return;
    int t0 = (blockIdx.x & 31) * 128;
    int g = d_woG[wi];
    int gs = d_gstart[g], gc = d_gcount[g];
    int a0 = d_woA[wi] * 128;

    __shared__ float Cs[8][132], Xs[8][132];
    int tid = threadIdx.x, ty = tid >> 4, tx = tid & 15;

    unsigned long long acc[8][4];
#pragma unroll
    for (int r = 0; r < 8; r++)
#pragma unroll
        for (int c = 0; c < 4; c++) acc[r][c] = 0ull;

    int lr = tid >> 1, lk = (tid & 1) * 4;       // Cs loader
    int xk = tid >> 5, xc = (tid & 31) * 4;      // Xs loader
    long long crow = (a0 + lr < gc) ? (long long)(gs + a0 + lr) * NRC : -1;

    for (int b0 = 0; b0 < gc; b0 += 8) {
        float4 vc = make_float4(0, 0, 0, 0);
        if (crow >= 0) {
            vc = *(const float4*)&d_scores[crow + b0 + lk];
            if (b0 + lk + 0 >= gc) vc.x = 0.f;
            if (b0 + lk + 1 >= gc) vc.y = 0.f;
            if (b0 + lk + 2 >= gc) vc.z = 0.f;
            if (b0 + lk + 3 >= gc) vc.w = 0.f;
        }
        int bm = b0 + xk;
        int vrow = (bm < gc) ? d_pnv[gs + bm] : 0;
        float4 vx = *(const float4*)&x[(long long)vrow * HW + t0 + xc];
        __syncthreads();
        Cs[lk + 0][lr] = vc.x; Cs[lk + 1][lr] = vc.y;
        Cs[lk + 2][lr] = vc.z; Cs[lk + 3][lr] = vc.w;
        *(float4*)&Xs[xk][xc] = vx;
        __syncthreads();
#pragma unroll
        for (int kk = 0; kk < 8; kk++) {
            unsigned long long ad[8], bd[4];
#pragma unroll
            for (int r = 0; r < 8; r++) ad[r] = dup2(Cs[kk][ty * 8 + r]);
#pragma unroll
            for (int c = 0; c < 4; c++)
                bd[c] = *(const unsigned long long*)&Xs[kk][tx * 8 + c * 2];
#pragma unroll
            for (int r = 0; r < 8; r++)
#pragma unroll
                for (int c = 0; c < 4; c++) fma2(acc[r][c], ad[r], bd[c]);
        }
    }

#pragma unroll
    for (int r = 0; r < 8; r++) {
        int al = a0 + ty * 8 + r;
        if (al >= gc) continue;
        int p = gs + al;
        int row = d_prow[p];
        float cst = d_cst[p];
        float* op = out + (long long)row * HW + t0 + tx * 8;
#pragma unroll
        for (int c = 0; c < 4; c++) {
            float2 v = unpk(acc[r][c]);
            op[c * 2]     = v.x + cst;
            op[c * 2 + 1] = v.y + cst;
        }
    }
}

// ---------------- launch ----------------
extern "C" void kernel_launch(void* const* d_in, const int* in_sizes, int n_in,
                              void* d_out, int out_size) {
    const float* x      = (const float*)d_in[0];
    const int*   labels = (const int*)d_in[1];
    const float* w      = (const float*)d_in[2];
    const float* bb     = (const float*)d_in[3];
    float* out = (float*)d_out;

    rowsumKernel<<<NR, 128>>>(x);
    scatterKernel<<<16, 128>>>(labels, w, bb);
    zeroInvalidKernel<<<NR, 128>>>(labels, out);
    scoresGemmKernel<<<MAXWS * 8, 256>>>(x);      // 4th launch -> ncu capture
    softmaxKernel<<<256, 256>>>();
    outGemmKernel<<<MAXWO * 32, 256>>>(x, out);
    (void)in_sizes; (void)n_in;
}

// round 5
// speedup vs baseline: 1.9496x; 1.2221x over previous
#include <cuda_runtime.h>

#define HW 4096
#define NR 2048
#define NL 16
#define NRC 256          // group-local column capacity
#define SPLITK 16

// ---------------- device scratch ----------------
__device__ float d_S[NR];
__device__ int   d_gcount[NL], d_gstart[NL];
__device__ int   d_nvalid;
__device__ int   d_prow[NR], d_pgrp[NR];
__device__ float d_pwq[NR], d_pbq[NR], d_pwk[NR], d_pbk[NR], d_pwv[NR], d_pbv[NR];
__device__ int   d_pmq[NR], d_pnk[NR], d_pnv[NR];
__device__ float d_pSq[NR], d_pSk[NR];
__device__ float d_cst[NR];
__device__ float d_scores[(long long)NR * NRC];              // 2 MB coeff matrix
__device__ float d_part[(long long)SPLITK * NR * NRC];       // 32 MB splitK partials

#define MAXWS 128
#define MAXWO 64
__device__ int d_wsG[MAXWS], d_wsA[MAXWS], d_wsB[MAXWS], d_nWorkS;
__device__ int d_woG[MAXWO], d_woA[MAXWO], d_nWorkO;

// ---------------- f32x2 helpers ----------------
__device__ __forceinline__ unsigned long long dup2(float v) {
    unsigned long long r;
    asm("mov.b64 %0, {%1, %1};" : "=l"(r) : "f"(v));
    return r;
}
__device__ __forceinline__ void fma2(unsigned long long &d, unsigned long long a,
                                     unsigned long long b) {
    asm("fma.rn.f32x2 %0, %1, %2, %0;" : "+l"(d) : "l"(a), "l"(b));
}
__device__ __forceinline__ float2 unpk(unsigned long long v) {
    float2 r;
    asm("mov.b64 {%0, %1}, %2;" : "=f"(r.x), "=f"(r.y) : "l"(v));
    return r;
}

// ---------------- rowsum ----------------
__global__ void rowsumKernel(const float* __restrict__ x) {
    int m = blockIdx.x;
    const float4* p = (const float4*)(x + (long long)m * HW);
    float s = 0.f;
    for (int i = threadIdx.x; i < HW / 4; i += 128) {
        float4 v = p[i];
        s += (v.x + v.y) + (v.z + v.w);
    }
    __shared__ float red[128];
    red[threadIdx.x] = s;
    __syncthreads();
    for (int o = 64; o > 0; o >>= 1) {
        if (threadIdx.x < o) red[threadIdx.x] += red[threadIdx.x + o];
        __syncthreads();
    }
    if (threadIdx.x == 0) d_S[m] = red[0];
}

// ---------------- scatter: self-contained setup + grouping ----------------
__global__ void scatterKernel(const int* __restrict__ labels,
                              const float* __restrict__ w,
                              const float* __restrict__ bb) {
    __shared__ int sl[NR];
    __shared__ int cnt[NL], sst[NL];
    int t = threadIdx.x;
    if (t < NL) cnt[t] = 0;
    for (int j = t; j < NR; j += 128) sl[j] = labels[j];
    __syncthreads();
    for (int j = t; j < NR; j += 128) {
        int l = sl[j];
        if (l >= 0) atomicAdd(&cnt[l], 1);
    }
    __syncthreads();
    if (t == 0) {
        int s = 0;
        for (int l = 0; l < NL; l++) { sst[l] = s; s += cnt[l]; }
        if (blockIdx.x == 0) {
            d_nvalid = s;
            for (int l = 0; l < NL; l++) { d_gcount[l] = cnt[l]; d_gstart[l] = sst[l]; }
            int n = 0;
            for (int l = 0; l < NL; l++) {
                int T = (cnt[l] + 127) / 128;
                for (int a = 0; a < T; a++)
                    for (int b = 0; b < T; b++)
                        if (n < MAXWS) { d_wsG[n] = l; d_wsA[n] = a; d_wsB[n] = b; n++; }
            }
            d_nWorkS = n;
            n = 0;
            for (int l = 0; l < NL; l++) {
                int T = (cnt[l] + 127) / 128;
                for (int a = 0; a < T; a++)
                    if (n < MAXWO) { d_woG[n] = l; d_woA[n] = a; n++; }
            }
            d_nWorkO = n;
        }
    }
    __syncthreads();
    int i = blockIdx.x * 128 + t;
    int l = sl[i];
    if (l < 0) return;
    int rank = 0;
    for (int j = 0; j < i; j++) rank += (sl[j] == l);
    int pos = sst[l] + rank;
    d_prow[pos] = i;
    d_pgrp[pos] = l;
    int jq = i % 768;            int mq = (i / 768) * 256 + jq / 3;
    int rk = i + 2048; int jk = rk % 768; int nk = (rk / 768) * 256 + jk / 3;
    int rv = i + 4096; int jv = rv % 768; int nv = (rv / 768) * 256 + jv / 3;
    d_pwq[pos] = w[jq]; d_pbq[pos] = bb[jq];
    d_pwk[pos] = w[jk]; d_pbk[pos] = bb[jk];
    d_pwv[pos] = w[jv]; d_pbv[pos] = bb[jv];
    d_pmq[pos] = mq; d_pnk[pos] = nk; d_pnv[pos] = nv;
    d_pSq[pos] = d_S[mq]; d_pSk[pos] = d_S[nk];
}

// ---------------- zero only invalid output rows ----------------
__global__ void zeroInvalidKernel(const int* __restrict__ labels,
                                  float* __restrict__ out) {
    int i = blockIdx.x;
    if (labels[i] >= 0) return;
    float4* p = (float4*)(out + (long long)i * HW);
    float4 z = make_float4(0, 0, 0, 0);
    for (int j = threadIdx.x; j < HW / 4; j += 128) p[j] = z;
}

// ---------------- scores GEMM: splitK=16, conflict-free frags ------------
// cols: {tx*4..tx*4+3, 64+tx*4..64+tx*4+3} as packed f32x2 via ulonglong2
// rows: ty*8..ty*8+7 via two broadcast float4 + dup2
__global__ __launch_bounds__(256) void scoresGemmKernel(const float* __restrict__ x) {
    int wi = blockIdx.x >> 4;
    int ks = blockIdx.x & 15;
    if (wi >= d_nWorkS) return;
    int g = d_wsG[wi];
    int gs = d_gstart[g], gc = d_gcount[g];
    int a0 = d_wsA[wi] * 128, b0 = d_wsB[wi] * 128;
    int k0b = ks * (HW / SPLITK);

    __shared__ float As[8][132], Bs[8][132];
    int tid = threadIdx.x;
    int ty = tid >> 4, tx = tid & 15;

    unsigned long long acc[8][4];
#pragma unroll
    for (int r = 0; r < 8; r++)
#pragma unroll
        for (int c = 0; c < 4; c++) acc[r][c] = 0ull;

    int lr = tid >> 1, lk = (tid & 1) * 4;
    const float* ap  = (a0 + lr < gc) ? x + (long long)d_pmq[gs + a0 + lr] * HW : 0;
    const float* bpp = (b0 + lr < gc) ? x + (long long)d_pnk[gs + b0 + lr] * HW : 0;

    for (int kc = 0; kc < (HW / SPLITK) / 8; kc++) {
        int k0 = k0b + kc * 8 + lk;
        float4 va = ap  ? *(const float4*)(ap  + k0) : make_float4(0, 0, 0, 0);
        float4 vb = bpp ? *(const float4*)(bpp + k0) : make_float4(0, 0, 0, 0);
        __syncthreads();
        As[lk + 0][lr] = va.x; As[lk + 1][lr] = va.y;
        As[lk + 2][lr] = va.z; As[lk + 3][lr] = va.w;
        Bs[lk + 0][lr] = vb.x; Bs[lk + 1][lr] = vb.y;
        Bs[lk + 2][lr] = vb.z; Bs[lk + 3][lr] = vb.w;
        __syncthreads();
#pragma unroll
        for (int kk = 0; kk < 8; kk++) {
            float4 aLo = *(const float4*)&As[kk][ty * 8];
            float4 aHi = *(const float4*)&As[kk][ty * 8 + 4];
            ulonglong2 u0 = *(const ulonglong2*)&Bs[kk][tx * 4];
            ulonglong2 u1 = *(const ulonglong2*)&Bs[kk][64 + tx * 4];
            unsigned long long bd[4] = { u0.x, u0.y, u1.x, u1.y };
            unsigned long long ad[8] = { dup2(aLo.x), dup2(aLo.y), dup2(aLo.z), dup2(aLo.w),
                                         dup2(aHi.x), dup2(aHi.y), dup2(aHi.z), dup2(aHi.w) };
#pragma unroll
            for (int r = 0; r < 8; r++)
#pragma unroll
                for (int c = 0; c < 4; c++) fma2(acc[r][c], ad[r], bd[c]);
        }
    }

    // store raw Gram partials (wq/wk scaling folded into softmax)
    long long kbase = (long long)ks * NR * NRC;
#pragma unroll
    for (int r = 0; r < 8; r++) {
        int al = a0 + ty * 8 + r;
        if (al >= gc) continue;
        long long ro = kbase + (long long)(gs + al) * NRC;
#pragma unroll
        for (int c = 0; c < 4; c++) {
            int col = b0 + ((c < 2) ? tx * 4 + c * 2 : 64 + tx * 4 + (c - 2) * 2);
            if (col + 1 < gc) {
                *(unsigned long long*)&d_part[ro + col] = acc[r][c];
            } else if (col < gc) {
                d_part[ro + col] = unpk(acc[r][c]).x;
            }
        }
    }
}

// ---------------- softmax: 16-way partial sum + affine + softmax + wv ----
__global__ void softmaxKernel() {
    int p = blockIdx.x * 8 + (threadIdx.x >> 5);
    int lane = threadIdx.x & 31;
    if (p >= d_nvalid) return;
    int g = d_pgrp[p], gs = d_gstart[g], gc = d_gcount[g];
    long long ro = (long long)p * NRC;

    float wq = d_pwq[p], bq = d_pbq[p];
    float A2 = wq * d_pSq[p] + bq * (float)HW;   // coeff of bk_q

    float m = -3.4e38f;
    for (int bl = lane; bl < gc; bl += 32) {
        float gsum = 0.f;
#pragma unroll
        for (int s = 0; s < SPLITK; s++) gsum += d_part[(long long)s * NR * NRC + ro + bl];
        int q = gs + bl;
        float val = d_pwk[q] * (wq * gsum + bq * d_pSk[q]) + A2 * d_pbk[q];
        d_scores[ro + bl] = val;
        m = fmaxf(m, val);
    }
#pragma unroll
    for (int o = 16; o > 0; o >>= 1) m = fmaxf(m, __shfl_xor_sync(0xffffffffu, m, o));

    float sum = 0.f, cs = 0.f;
    for (int bl = lane; bl < gc; bl += 32) {
        float e = expf(d_scores[ro + bl] - m);
        d_scores[ro + bl] = e;
        sum += e;
        cs += e * d_pbv[gs + bl];
    }
#pragma unroll
    for (int o = 16; o > 0; o >>= 1) {
        sum += __shfl_xor_sync(0xffffffffu, sum, o);
        cs  += __shfl_xor_sync(0xffffffffu, cs, o);
    }
    float inv = 1.0f / sum;
    for (int bl = lane; bl < gc; bl += 32)
        d_scores[ro + bl] *= inv * d_pwv[gs + bl];
    if (lane == 0) d_cst[p] = cs * inv;
}

// ---------------- out GEMM: coeff (g x g) @ Xv (g x 4096) ----------------
__global__ __launch_bounds__(256) void outGemmKernel(const float* __restrict__ x,
                                                     float* __restrict__ out) {
    int wi = blockIdx.x >> 5;
    if (wi >= d_nWorkO) return;
    int t0 = (blockIdx.x & 31) * 128;
    int g = d_woG[wi];
    int gs = d_gstart[g], gc = d_gcount[g];
    int a0 = d_woA[wi] * 128;

    __shared__ float Cs[8][132], Xs[8][132];
    int tid = threadIdx.x, ty = tid >> 4, tx = tid & 15;

    unsigned long long acc[8][4];
#pragma unroll
    for (int r = 0; r < 8; r++)
#pragma unroll
        for (int c = 0; c < 4; c++) acc[r][c] = 0ull;

    int lr = tid >> 1, lk = (tid & 1) * 4;       // Cs loader
    int xk = tid >> 5, xc = (tid & 31) * 4;      // Xs loader
    long long crow = (a0 + lr < gc) ? (long long)(gs + a0 + lr) * NRC : -1;

    for (int b0 = 0; b0 < gc; b0 += 8) {
        float4 vc = make_float4(0, 0, 0, 0);
        if (crow >= 0) {
            vc = *(const float4*)&d_scores[crow + b0 + lk];
            if (b0 + lk + 0 >= gc) vc.x = 0.f;
            if (b0 + lk + 1 >= gc) vc.y = 0.f;
            if (b0 + lk + 2 >= gc) vc.z = 0.f;
            if (b0 + lk + 3 >= gc) vc.w = 0.f;
        }
        int bm = b0 + xk;
        int vrow = (bm < gc) ? d_pnv[gs + bm] : 0;
        float4 vx = *(const float4*)&x[(long long)vrow * HW + t0 + xc];
        __syncthreads();
        Cs[lk + 0][lr] = vc.x; Cs[lk + 1][lr] = vc.y;
        Cs[lk + 2][lr] = vc.z; Cs[lk + 3][lr] = vc.w;
        *(float4*)&Xs[xk][xc] = vx;
        __syncthreads();
#pragma unroll
        for (int kk = 0; kk < 8; kk++) {
            float4 aLo = *(const float4*)&Cs[kk][ty * 8];
            float4 aHi = *(const float4*)&Cs[kk][ty * 8 + 4];
            ulonglong2 u0 = *(const ulonglong2*)&Xs[kk][tx * 4];
            ulonglong2 u1 = *(const ulonglong2*)&Xs[kk][64 + tx * 4];
            unsigned long long bd[4] = { u0.x, u0.y, u1.x, u1.y };
            unsigned long long ad[8] = { dup2(aLo.x), dup2(aLo.y), dup2(aLo.z), dup2(aLo.w),
                                         dup2(aHi.x), dup2(aHi.y), dup2(aHi.z), dup2(aHi.w) };
#pragma unroll
            for (int r = 0; r < 8; r++)
#pragma unroll
                for (int c = 0; c < 4; c++) fma2(acc[r][c], ad[r], bd[c]);
        }
    }

#pragma unroll
    for (int r = 0; r < 8; r++) {
        int al = a0 + ty * 8 + r;
        if (al >= gc) continue;
        int p = gs + al;
        int row = d_prow[p];
        float cst = d_cst[p];
        float* op = out + (long long)row * HW + t0;
#pragma unroll
        for (int c = 0; c < 4; c++) {
            float2 v = unpk(acc[r][c]);
            int col = (c < 2) ? tx * 4 + c * 2 : 64 + tx * 4 + (c - 2) * 2;
            op[col]     = v.x + cst;
            op[col + 1] = v.y + cst;
        }
    }
}

// ---------------- launch ----------------
extern "C" void kernel_launch(void* const* d_in, const int* in_sizes, int n_in,
                              void* d_out, int out_size) {
    const float* x      = (const float*)d_in[0];
    const int*   labels = (const int*)d_in[1];
    const float* w      = (const float*)d_in[2];
    const float* bb     = (const float*)d_in[3];
    float* out = (float*)d_out;

    rowsumKernel<<<NR, 128>>>(x);
    scatterKernel<<<16, 128>>>(labels, w, bb);
    zeroInvalidKernel<<<NR, 128>>>(labels, out);
    scoresGemmKernel<<<MAXWS * SPLITK, 256>>>(x);   // 4th launch -> ncu capture
    softmaxKernel<<<256, 256>>>();
    outGemmKernel<<<MAXWO * 32, 256>>>(x, out);
    (void)in_sizes; (void)n_in;
}